// round 13
// baseline (speedup 1.0000x reference)
#include <cuda_runtime.h>
#include <cuda_fp16.h>
#include <cstdint>
#include <math.h>

#define HIDDEN   1024
#define BATCH    512
#define FEAT     1024
#define TSTEPS   100
#define TIME_TOT 103
#define FOURH    4096
#define MTOT     (TSTEPS * BATCH)   // 51200

// A-only stages: 4 x 32KB
#define STG_B    32768
#define SMEM_SZ  (4 * STG_B)        // 131072

// ------------------------------ scratch (device globals, no allocs) ----------
__device__ __align__(16) __half g_WRp[32 * 32 * 8192];           // [W;R] fp16 per-strip (16MB)
// xp padded by one extra step (512 batch rows) for the t=99,kt=15 tail prefetch
__device__ __align__(16) __half g_xp[((size_t)MTOT + 512) * 1024];
__device__ __align__(16) __half g_hp[2][BATCH * HIDDEN];         // permuted h fp16 ping-pong
__device__ unsigned g_sync4[4];                                  // per-by-group counters

// ------------------------------ asm helpers ----------------------------------
#define CP16(dst, src) \
    asm volatile("cp.async.cg.shared.global [%0], [%1], 16;" :: "r"(dst), "l"(src))
#define CP_COMMIT() asm volatile("cp.async.commit_group;" ::: "memory")
#define CP_WAIT2()  asm volatile("cp.async.wait_group 2;" ::: "memory")

__device__ __forceinline__ uint4 lds128u(uint32_t a) {
    uint4 v;
    asm volatile("ld.shared.v4.b32 {%0,%1,%2,%3}, [%4];"
                 : "=r"(v.x), "=r"(v.y), "=r"(v.z), "=r"(v.w) : "r"(a));
    return v;
}
// L1-bypassing 8B global load (coherent with peer-SM h writes via L2)
__device__ __forceinline__ uint2 ldg_cg64(const char* p) {
    uint2 v;
    asm volatile("ld.global.cg.v2.u32 {%0,%1}, [%2];" : "=r"(v.x), "=r"(v.y) : "l"(p));
    return v;
}
__device__ __forceinline__ void mma_f16(float c[4], uint4 a, uint2 b) {
    asm volatile(
        "mma.sync.aligned.m16n8k16.row.col.f32.f16.f16.f32 "
        "{%0,%1,%2,%3}, {%4,%5,%6,%7}, {%8,%9}, {%0,%1,%2,%3};"
        : "+f"(c[0]), "+f"(c[1]), "+f"(c[2]), "+f"(c[3])
        : "r"(a.x), "r"(a.y), "r"(a.z), "r"(a.w), "r"(b.x), "r"(b.y));
}

// fast transcendentals
__device__ __forceinline__ float sigm_f(float z) {
    return __fdividef(1.f, 1.f + __expf(-z));
}
__device__ __forceinline__ float tanh_f(float z) {
    return 1.f - __fdividef(2.f, __expf(2.f * z) + 1.f);
}

// ------------------------------ prep (single launch) --------------------------
#define N1 (32 * 32 * 4096)          // WRp half2 elems
#define N2 (MTOT * 1024 / 16)        // xp 16-float chunks
#define N3 (BATCH * HIDDEN / 2)      // hp[0] zero words

__global__ void prep_all(const float* __restrict__ W, const float* __restrict__ R,
                         const float* __restrict__ x)
{
    int idx = blockIdx.x * blockDim.x + threadIdx.x;
    if (idx < N1) {
        int v   = idx & 3;
        int tig = (idx >> 2) & 3;
        int grp = (idx >> 4) & 7;
        int k16 = (idx >> 7) & 3;
        int mi  = (idx >> 9) & 3;
        int wm  = (idx >> 11) & 1;
        int kt  = (idx >> 12) & 31;
        int cb  = idx >> 17;
        int r8  = v & 1;
        int khi = (v >> 1) * 8;
        int q   = mi * 2 + r8;
        int gate = q & 3;
        int jhi  = q >> 2;
        int j = cb * 32 + wm * 16 + jhi * 8 + grp;
        int kl = k16 * 16 + khi + 2 * tig;
        const float* src = (kt < 16) ? W : R;
        int k = (kt < 16 ? kt : kt - 16) * 64 + kl;
        int col = gate * 1024 + j;
        ((__half2*)g_WRp)[idx] = __floats2half2_rn(src[(size_t)k * FOURH + col],
                                                   src[(size_t)(k + 1) * FOURH + col]);
    } else if (idx < N1 + N2) {
        int id = idx - N1;
        int grp = id & 7;
        int k16 = (id >> 3) & 3;
        int kt  = (id >> 5) & 15;
        int blk = id >> 9;
        int m = blk * 8 + grp;
        int t = m >> 9, bb = m & 511;
        const float* s = x + ((size_t)bb * TIME_TOT + t) * FEAT + kt * 64 + k16 * 16;
        float f[16];
#pragma unroll
        for (int qd = 0; qd < 4; qd++) *(float4*)(f + qd * 4) = *(const float4*)(s + qd * 4);
        __half2 o[8];
#pragma unroll
        for (int tg = 0; tg < 4; tg++)
#pragma unroll
            for (int rg = 0; rg < 2; rg++)
                o[tg * 2 + rg] = __floats2half2_rn(f[rg * 8 + 2 * tg], f[rg * 8 + 2 * tg + 1]);
        __half2* d = (__half2*)g_xp + (size_t)blk * 4096 + kt * 256 + k16 * 64 + grp * 8;
        *(uint4*)d = *(uint4*)o;
        *(uint4*)(d + 4) = *(uint4*)(o + 4);
    } else if (idx < N1 + N2 + N3) {
        ((uint32_t*)g_hp)[idx - N1 - N2] = 0u;     // zero hp[0]
    } else if (idx < N1 + N2 + N3 + 4) {
        g_sync4[idx - N1 - N2 - N3] = 0u;
    }
}

// ------------------------------ pipeline pieces -------------------------------
// A stage (32KB, weights only): [sub(2):16384][wm:8192][mi:2048][k16:512][grp:64][tig:16]
#define ISSUE_A(s, K) do {                                                        \
    uint32_t _stA = sb + (uint32_t)(s) * STG_B;                                   \
    const char* _as = Abase + (size_t)(K) * 32768;                                \
    _Pragma("unroll")                                                             \
    for (int _r = 0; _r < 8; _r++) {                                              \
        int _id = tid + _r * 256;                                                 \
        CP16(_stA + _id * 16, _as + _id * 16);                                    \
    }                                                                             \
} while (0)

// B fragment source: global, fragment-ordered. For (K, sub):
//   addr = (K<8 ? Bx+K*2048 : Bh+(K-8)*2048) + sub*1024 + nj*16384 + kk*256 + bthr
__device__ __forceinline__ const char* bptr(const char* Bx, const char* Bh,
                                            int K, int sub, size_t bthr) {
    const char* base = (K < 8) ? (Bx + (size_t)K * 2048) : (Bh + (size_t)(K - 8) * 2048);
    return base + sub * 1024 + bthr;
}
#define PREFETCH_B(dst, srcp) do {                                                \
    _Pragma("unroll")                                                             \
    for (int _nj = 0; _nj < 4; _nj++)                                             \
        _Pragma("unroll")                                                         \
        for (int _kk = 0; _kk < 4; _kk++)                                         \
            (dst)[_nj][_kk] = ldg_cg64((srcp) + (size_t)_nj * 16384 + _kk * 256); \
} while (0)

// Compute one half-ktile (4 k16) from A smem stage st + B register buffer.
#define COMPUTE_SUB(st, Bbuf, sub) do {                                           \
    uint32_t _aB = sb + (uint32_t)(st) * STG_B + (uint32_t)(sub) * 16384u         \
                 + wm * 8192u + grp * 64u + tig * 16u;                            \
    _Pragma("unroll")                                                             \
    for (int _k = 0; _k < 4; _k++) {                                              \
        uint4 _af[4];                                                             \
        _Pragma("unroll")                                                         \
        for (int _mi = 0; _mi < 4; _mi++)                                         \
            _af[_mi] = lds128u(_aB + _k * 512u + _mi * 2048u);                    \
        _Pragma("unroll")                                                         \
        for (int _mi = 0; _mi < 4; _mi++)                                         \
            _Pragma("unroll")                                                     \
            for (int _nj = 0; _nj < 4; _nj++)                                     \
                mma_f16(acc[_mi][_nj], _af[_mi], (Bbuf)[_nj][_k]);                \
    }                                                                             \
} while (0)

// ------------------------------ persistent fused LSTM -------------------------
// grid (32,4): cb = 32-hidden strip, by = 128-batch block. 1 CTA/SM, resident.
// A: shared-memory 4-stage pipeline (weights, period-16 so stage = K&3 is
// phase-stable). B: direct global->register fragments, half-ktile lookahead.
__global__ void __launch_bounds__(256, 1)
lstm_persist(const float* __restrict__ bias, float* __restrict__ out)
{
    extern __shared__ char smem[];
    const uint32_t sb = (uint32_t)__cvta_generic_to_shared(smem);
    const int tid = threadIdx.x, lane = tid & 31, wid = tid >> 5;
    const int wm = wid >> 2, wn = wid & 3;
    const int grp = lane >> 2, tig = lane & 3;
    const int cb = blockIdx.x, by = blockIdx.y;

    const char* Abase = (const char*)g_WRp + (size_t)cb * 524288;
    const size_t bthr = (size_t)(wn * 4) * 16384 + grp * 32 + tig * 8;
    const size_t bblk0 = (size_t)(by * 16) * 16384;

    const int j0 = cb * 32 + wm * 16;
    float bia[2][4];
#pragma unroll
    for (int jhi = 0; jhi < 2; jhi++) {
        const int j = j0 + jhi * 8 + grp;
        bia[jhi][0] = __ldg(bias + j);
        bia[jhi][1] = __ldg(bias + 1024 + j);
        bia[jhi][2] = __ldg(bias + 2048 + j);
        bia[jhi][3] = __ldg(bias + 3072 + j);
    }
    float cr[2][4][2];
#pragma unroll
    for (int a = 0; a < 2; a++)
#pragma unroll
        for (int b = 0; b < 4; b++) { cr[a][b][0] = 0.f; cr[a][b][1] = 0.f; }

    uint2 Bb0[4][4], Bb1[4][4];

    // prologue: A ktiles 0,1,2 -> stages 0,1,2; B (t=0, K=0, sub0)
    ISSUE_A(0, 0); CP_COMMIT();
    ISSUE_A(1, 1); CP_COMMIT();
    ISSUE_A(2, 2); CP_COMMIT();
    {
        const char* Bx0 = (const char*)g_xp + bblk0;
        const char* Bh0 = (const char*)g_hp[0] + bblk0;
        PREFETCH_B(Bb0, bptr(Bx0, Bh0, 0, 0, bthr));
    }

    for (int t = 0; t < TSTEPS; t++) {
        const char* Bx  = (const char*)g_xp + (size_t)t * 64 * 16384 + bblk0;
        const char* Bh  = (const char*)g_hp[t & 1] + bblk0;
        const char* BxN = Bx + (size_t)64 * 16384;
        __half* hw = g_hp[(t & 1) ^ 1];

        float acc[4][4][4];
#pragma unroll
        for (int a = 0; a < 4; a++)
#pragma unroll
            for (int b = 0; b < 4; b++)
#pragma unroll
                for (int c = 0; c < 4; c++) acc[a][b][c] = 0.f;

        for (int kt = 0; kt < 16; kt++) {
            CP_WAIT2();                 // A stage kt landed (2 groups in flight)
            __syncthreads();
            if (kt == 7 && t > 0) {
                // B prefetch for ktile 8 (first h tile) is issued THIS iteration
                const unsigned tgt = (unsigned)t * 32u;
                while (*(volatile unsigned*)&g_sync4[by] < tgt) { }
                __threadfence();
            }
            // A issue (weights are step-periodic: K = la mod 16, stage = la mod 4)
            const int la = kt + 3;
            if (la < 16 || t + 1 < TSTEPS) ISSUE_A(la & 3, la & 15);
            CP_COMMIT();

            // B: prefetch sub1 of this ktile, compute sub0
            PREFETCH_B(Bb1, bptr(Bx, Bh, kt, 1, bthr));
            COMPUTE_SUB(kt & 3, Bb0, 0);
            // B: prefetch sub0 of next ktile (or next step's K=0, x-phase)
            if (kt < 15) {
                PREFETCH_B(Bb0, bptr(Bx, Bh, kt + 1, 0, bthr));
            } else {
                PREFETCH_B(Bb0, BxN + bthr);   // K=0, sub=0 of t+1 (xp padded)
            }
            COMPUTE_SUB(kt & 3, Bb1, 1);
        }

        // ---- fused LSTM epilogue (c in registers) ----
        float hnv[2][4][2];
#pragma unroll
        for (int jhi = 0; jhi < 2; jhi++) {
            const int j = j0 + jhi * 8 + grp;
            const int kt_  = j >> 6;
            const int k16_ = (j >> 4) & 3;
            const int reg_ = (j >> 3) & 1;
            const int tig_ = (j >> 1) & 3;
            const int u_   = j & 1;
            const int jbase = (kt_ * 4 + k16_) * 32;
#pragma unroll
            for (int nj = 0; nj < 4; nj++) {
                const int blk = by * 16 + wn * 4 + nj;
#pragma unroll
                for (int e = 0; e < 2; e++) {
                    const int grp_b = tig * 2 + e;
                    float zi = acc[2 * jhi    ][nj][e]     + bia[jhi][0];
                    float zf = acc[2 * jhi    ][nj][2 + e] + bia[jhi][1];
                    float zg = acc[2 * jhi + 1][nj][e]     + bia[jhi][2];
                    float zo = acc[2 * jhi + 1][nj][2 + e] + bia[jhi][3];

                    float si = sigm_f(zi);
                    float sf = sigm_f(zf);
                    float so = sigm_f(zo);
                    float tg = tanh_f(zg);

                    float cn = sf * cr[jhi][nj][e] + si * tg;
                    float hn = so * tanh_f(cn);
                    cr[jhi][nj][e] = cn;
                    hnv[jhi][nj][e] = hn;
                    hw[(size_t)blk * 8192 + (jbase + grp_b * 4 + tig_) * 4 + reg_ * 2 + u_] =
                        __float2half_rn(hn);
                }
            }
        }

        // publish h, arrive, then out stores (off the h critical path)
        __syncthreads();
        if (tid == 0) {
            __threadfence();
            atomicAdd(&g_sync4[by], 1u);
        }

#pragma unroll
        for (int jhi = 0; jhi < 2; jhi++) {
            const int j = j0 + jhi * 8 + grp;
#pragma unroll
            for (int nj = 0; nj < 4; nj++) {
                const int blk = by * 16 + wn * 4 + nj;
#pragma unroll
                for (int e = 0; e < 2; e++) {
                    const int b = blk * 8 + tig * 2 + e;
                    out[(size_t)b * (TSTEPS * HIDDEN) + (size_t)t * 1024 + j] = hnv[jhi][nj][e];
                }
            }
        }
    }
}

// ------------------------------ launch ----------------------------------------
extern "C" void kernel_launch(void* const* d_in, const int* in_sizes, int n_in,
                              void* d_out, int out_size)
{
    const float* x    = (const float*)d_in[0];  // [512, 103, 1024]
    const float* W    = (const float*)d_in[1];  // [1024, 4096]
    const float* R    = (const float*)d_in[2];  // [1024, 4096]
    const float* bias = (const float*)d_in[3];  // [4096]
    float* out = (float*)d_out;                 // [512, 100, 1024]

    cudaFuncSetAttribute(lstm_persist, cudaFuncAttributeMaxDynamicSharedMemorySize, SMEM_SZ);

    const int total = N1 + N2 + N3 + 4;
    prep_all<<<(total + 255) / 256, 256>>>(W, R, x);

    dim3 grid(32, 4);   // 128 CTAs, 1/SM, co-resident
    lstm_persist<<<grid, 256, SMEM_SZ>>>(bias, out);
}

// round 14
// speedup vs baseline: 1.2396x; 1.2396x over previous
#include <cuda_runtime.h>
#include <cuda_fp16.h>
#include <cstdint>
#include <math.h>

#define HIDDEN   1024
#define BATCH    512
#define FEAT     1024
#define TSTEPS   100
#define TIME_TOT 103
#define FOURH    4096
#define MTOT     (TSTEPS * BATCH)   // 51200

// smem map: X A-stages 2x32KB @0 | H stages 2x(A32+B32)KB @65536 | z 32KB @196608
#define XS(s)    (sb + (uint32_t)(s) * 32768u)
#define HS(s)    (sb + 65536u + (uint32_t)(s) * 65536u)
#define ZOFF     196608u
#define SMEM_SZ  229376

// ------------------------------ scratch (device globals, no allocs) ----------
__device__ __align__(16) __half g_WRp[32 * 32 * 8192];           // [W;R] per-strip (16MB)
__device__ __align__(16) __half g_xp[((size_t)MTOT + 512) * 1024]; // padded 1 step
__device__ __align__(16) __half g_hp[2][BATCH * HIDDEN];         // permuted h ping-pong
__device__ unsigned g_sync4[4];                                  // per-by counters

// ------------------------------ asm helpers ----------------------------------
#define CP16(dst, src) \
    asm volatile("cp.async.cg.shared.global [%0], [%1], 16;" :: "r"(dst), "l"(src))
#define CP_COMMIT() asm volatile("cp.async.commit_group;" ::: "memory")
#define CP_WAIT0()  asm volatile("cp.async.wait_group 0;" ::: "memory")
#define BAR_SYNC(id, cnt) asm volatile("bar.sync %0, %1;"   :: "r"(id), "r"(cnt) : "memory")
#define BAR_ARRV(id, cnt) asm volatile("bar.arrive %0, %1;" :: "r"(id), "r"(cnt) : "memory")

__device__ __forceinline__ uint4 lds128u(uint32_t a) {
    uint4 v;
    asm volatile("ld.shared.v4.b32 {%0,%1,%2,%3}, [%4];"
                 : "=r"(v.x), "=r"(v.y), "=r"(v.z), "=r"(v.w) : "r"(a));
    return v;
}
__device__ __forceinline__ void sts128(uint32_t a, uint4 v) {
    asm volatile("st.shared.v4.b32 [%0], {%1,%2,%3,%4};"
                 :: "r"(a), "r"(v.x), "r"(v.y), "r"(v.z), "r"(v.w) : "memory");
}
__device__ __forceinline__ uint2 lds64u(uint32_t a) {
    uint2 v;
    asm volatile("ld.shared.v2.b32 {%0,%1}, [%2];" : "=r"(v.x), "=r"(v.y) : "r"(a));
    return v;
}
__device__ __forceinline__ uint2 ldg_cg64(const char* p) {
    uint2 v;
    asm volatile("ld.global.cg.v2.u32 {%0,%1}, [%2];" : "=r"(v.x), "=r"(v.y) : "l"(p));
    return v;
}
__device__ __forceinline__ void mma_f16(float c[4], uint4 a, uint2 b) {
    asm volatile(
        "mma.sync.aligned.m16n8k16.row.col.f32.f16.f16.f32 "
        "{%0,%1,%2,%3}, {%4,%5,%6,%7}, {%8,%9}, {%0,%1,%2,%3};"
        : "+f"(c[0]), "+f"(c[1]), "+f"(c[2]), "+f"(c[3])
        : "r"(a.x), "r"(a.y), "r"(a.z), "r"(a.w), "r"(b.x), "r"(b.y));
}
__device__ __forceinline__ float sigm_f(float z) {
    return __fdividef(1.f, 1.f + __expf(-z));
}
__device__ __forceinline__ float tanh_f(float z) {
    return 1.f - __fdividef(2.f, __expf(2.f * z) + 1.f);
}
__device__ __forceinline__ uint32_t packh2(float a, float b) {
    __half2 h = __floats2half2_rn(a, b);
    return *(uint32_t*)&h;
}
__device__ __forceinline__ float2 unph2(uint32_t u) {
    return __half22float2(*(__half2*)&u);
}

// ------------------------------ prep (single launch) --------------------------
#define N1 (32 * 32 * 4096)
#define N2 (MTOT * 1024 / 16)
#define N3 (BATCH * HIDDEN / 2)

__global__ void prep_all(const float* __restrict__ W, const float* __restrict__ R,
                         const float* __restrict__ x)
{
    int idx = blockIdx.x * blockDim.x + threadIdx.x;
    if (idx < N1) {
        int v   = idx & 3;
        int tig = (idx >> 2) & 3;
        int grp = (idx >> 4) & 7;
        int k16 = (idx >> 7) & 3;
        int mi  = (idx >> 9) & 3;
        int wm  = (idx >> 11) & 1;
        int kt  = (idx >> 12) & 31;
        int cb  = idx >> 17;
        int r8  = v & 1;
        int khi = (v >> 1) * 8;
        int q   = mi * 2 + r8;
        int gate = q & 3;
        int jhi  = q >> 2;
        int j = cb * 32 + wm * 16 + jhi * 8 + grp;
        int kl = k16 * 16 + khi + 2 * tig;
        const float* src = (kt < 16) ? W : R;
        int k = (kt < 16 ? kt : kt - 16) * 64 + kl;
        int col = gate * 1024 + j;
        ((__half2*)g_WRp)[idx] = __floats2half2_rn(src[(size_t)k * FOURH + col],
                                                   src[(size_t)(k + 1) * FOURH + col]);
    } else if (idx < N1 + N2) {
        int id = idx - N1;
        int grp = id & 7;
        int k16 = (id >> 3) & 3;
        int kt  = (id >> 5) & 15;
        int blk = id >> 9;
        int m = blk * 8 + grp;
        int t = m >> 9, bb = m & 511;
        const float* s = x + ((size_t)bb * TIME_TOT + t) * FEAT + kt * 64 + k16 * 16;
        float f[16];
#pragma unroll
        for (int qd = 0; qd < 4; qd++) *(float4*)(f + qd * 4) = *(const float4*)(s + qd * 4);
        __half2 o[8];
#pragma unroll
        for (int tg = 0; tg < 4; tg++)
#pragma unroll
            for (int rg = 0; rg < 2; rg++)
                o[tg * 2 + rg] = __floats2half2_rn(f[rg * 8 + 2 * tg], f[rg * 8 + 2 * tg + 1]);
        __half2* d = (__half2*)g_xp + (size_t)blk * 4096 + kt * 256 + k16 * 64 + grp * 8;
        *(uint4*)d = *(uint4*)o;
        *(uint4*)(d + 4) = *(uint4*)(o + 4);
    } else if (idx < N1 + N2 + N3) {
        ((uint32_t*)g_hp)[idx - N1 - N2] = 0u;
    } else if (idx < N1 + N2 + N3 + 4) {
        g_sync4[idx - N1 - N2 - N3] = 0u;
    }
}

// ------------------------------ persistent warp-specialized LSTM --------------
// grid (32,4), 256 thr. Warps 0-3 (X): zx = x_t @ W (K ktiles 0-7), no h dep,
// runs one step ahead; B direct from global. Warps 4-7 (H): zh = h_t @ R
// (ktiles 8-15) via cp.async pipe, + zx (fp16 smem buffer), epilogue, h publish.
// Named bars: 1 = H internal, 2 = X internal, 3 = z-ready (X->H), 4 = z-free (H->X).
__global__ void __launch_bounds__(256, 1)
lstm_persist(const float* __restrict__ bias, float* __restrict__ out)
{
    extern __shared__ char smem[];
    const uint32_t sb = (uint32_t)__cvta_generic_to_shared(smem);
    const int tid = threadIdx.x, lane = tid & 31, wid = tid >> 5;
    const bool isX = (wid < 4);
    const int lw = isX ? wid : (wid - 4);
    const int wm = lw >> 1, wn = lw & 1;
    const int grp = lane >> 2, tig = lane & 3;
    const int cb = blockIdx.x, by = blockIdx.y;
    const int tl = tid & 127;

    const char* Abase = (const char*)g_WRp + (size_t)cb * 524288;
    const size_t bblk0 = (size_t)(by * 16) * 16384;
    const uint32_t zb = sb + ZOFF + (uint32_t)tl * 256u;

    if (isX) {
        // =================== X role: zx(t) producer =========================
        const size_t bthr = (size_t)(wn * 8) * 16384 + grp * 32 + tig * 8;
        uint2 Bb[2][8];

        // A issue: stage s gets W ktile K (32KB), by X's 128 threads
#define XISSUE(s, K) do {                                                       \
        uint32_t _d = XS(s);                                                    \
        const char* _a = Abase + (size_t)(K) * 32768;                           \
        _Pragma("unroll")                                                       \
        for (int _r = 0; _r < 16; _r++) {                                       \
            int _id = tl + _r * 128;                                            \
            CP16(_d + _id * 16, _a + _id * 16);                                 \
        }                                                                       \
} while (0)
#define PBLOAD(dst, base, u) do {                                               \
        const char* _p = (base) + ((u) >> 3) * 2048 + (((u) >> 2) & 1) * 1024   \
                       + ((u) & 3) * 256 + bthr;                                \
        _Pragma("unroll")                                                       \
        for (int _nj = 0; _nj < 8; _nj++)                                       \
            (dst)[_nj] = ldg_cg64(_p + (size_t)_nj * 16384);                    \
} while (0)

        const char* Bx = (const char*)g_xp + bblk0;
        XISSUE(0, 0); CP_COMMIT();
        PBLOAD(Bb[0], Bx, 0);

        for (int t = 0; t < TSTEPS; t++) {
            const char* BxN = Bx + 1048576;   // next step's x (padded at t=99)
            float acc[4][8][4];
#pragma unroll
            for (int a = 0; a < 4; a++)
#pragma unroll
                for (int b = 0; b < 8; b++)
#pragma unroll
                    for (int c = 0; c < 4; c++) acc[a][b][c] = 0.f;

            for (int kt = 0; kt < 8; kt++) {
                CP_WAIT0();
                BAR_SYNC(2, 128);
                XISSUE((kt + 1) & 1, (kt + 1) & 7);   // periodic weights
                CP_COMMIT();
#pragma unroll
                for (int q = 0; q < 8; q++) {
                    const int u = kt * 8 + q;
                    const int cur = u & 1, nxt = cur ^ 1;
                    const int nu = u + 1;
                    if (nu < 64) PBLOAD(Bb[nxt], Bx, nu);
                    else         PBLOAD(Bb[nxt], BxN, nu - 64);
                    uint32_t aB = XS(kt & 1) + (q >> 2) * 16384u + wm * 8192u
                                + (q & 3) * 512u + grp * 64u + tig * 16u;
                    uint4 af[4];
#pragma unroll
                    for (int mi = 0; mi < 4; mi++) af[mi] = lds128u(aB + mi * 2048u);
#pragma unroll
                    for (int mi = 0; mi < 4; mi++)
#pragma unroll
                        for (int nj = 0; nj < 8; nj++)
                            mma_f16(acc[mi][nj], af[mi], Bb[cur][nj]);
                }
            }

            // hand zx(t) to H: wait buffer free, store fp16, signal ready
            BAR_SYNC(4, 256);
#pragma unroll
            for (int mi = 0; mi < 4; mi++)
#pragma unroll
                for (int njp = 0; njp < 4; njp++) {
                    uint4 v;
                    v.x = packh2(acc[mi][2 * njp    ][0], acc[mi][2 * njp    ][1]);
                    v.y = packh2(acc[mi][2 * njp    ][2], acc[mi][2 * njp    ][3]);
                    v.z = packh2(acc[mi][2 * njp + 1][0], acc[mi][2 * njp + 1][1]);
                    v.w = packh2(acc[mi][2 * njp + 1][2], acc[mi][2 * njp + 1][3]);
                    sts128(zb + (mi * 4 + njp) * 16u, v);
                }
            BAR_ARRV(3, 256);
            Bx = BxN;
        }
        CP_WAIT0();   // drain tail A issue
    } else {
        // =================== H role: zh + z-add + epilogue ==================
#define HISSUE_A(s, K) do {                                                     \
        uint32_t _d = HS(s);                                                    \
        const char* _a = Abase + (size_t)(K) * 32768;                           \
        _Pragma("unroll")                                                       \
        for (int _r = 0; _r < 16; _r++) {                                       \
            int _id = tl + _r * 128;                                            \
            CP16(_d + _id * 16, _a + _id * 16);                                 \
        }                                                                       \
} while (0)
#define HISSUE_B(s, K, bhp) do {                                                \
        uint32_t _d = HS(s) + 32768u;                                           \
        const char* _b = (bhp) + (size_t)((K) - 8) * 2048;                      \
        _Pragma("unroll")                                                       \
        for (int _r = 0; _r < 16; _r++) {                                       \
            int _id = tl + _r * 128;                                            \
            CP16(_d + _id * 16,                                                 \
                 _b + (size_t)(_id >> 7) * 16384 + (size_t)(_id & 127) * 16);   \
        }                                                                       \
} while (0)

        const int j0 = cb * 32 + wm * 16;
        float bia[2][4];
#pragma unroll
        for (int jhi = 0; jhi < 2; jhi++) {
            const int j = j0 + jhi * 8 + grp;
            bia[jhi][0] = __ldg(bias + j);
            bia[jhi][1] = __ldg(bias + 1024 + j);
            bia[jhi][2] = __ldg(bias + 2048 + j);
            bia[jhi][3] = __ldg(bias + 3072 + j);
        }
        float cr[2][8][2];
#pragma unroll
        for (int a = 0; a < 2; a++)
#pragma unroll
            for (int b = 0; b < 8; b++) { cr[a][b][0] = 0.f; cr[a][b][1] = 0.f; }

        BAR_ARRV(4, 256);          // prime: z-buffer initially free
        HISSUE_A(0, 8); CP_COMMIT();   // prefetch R ktile 8 (t=0)

        for (int t = 0; t < TSTEPS; t++) {
            if (t > 0) {
                const unsigned tgt = (unsigned)t * 32u;
                while (*(volatile unsigned*)&g_sync4[by] < tgt) { }
                __threadfence();
            }
            const char* Bh = (const char*)g_hp[t & 1] + bblk0;
            __half* hw = g_hp[(t & 1) ^ 1];

            HISSUE_B(0, 8, Bh); CP_COMMIT();   // A half already prefetched

            float acc[4][8][4];
#pragma unroll
            for (int a = 0; a < 4; a++)
#pragma unroll
                for (int b = 0; b < 8; b++)
#pragma unroll
                    for (int c = 0; c < 4; c++) acc[a][b][c] = 0.f;

            for (int kt = 0; kt < 8; kt++) {
                CP_WAIT0();
                BAR_SYNC(1, 128);
                if (kt < 7) {
                    HISSUE_A((kt + 1) & 1, 9 + kt);
                    HISSUE_B((kt + 1) & 1, 9 + kt, Bh);
                } else {
                    HISSUE_A(0, 8);        // next step's R ktile 8 into free stage 0
                }
                CP_COMMIT();
                const uint32_t st = (uint32_t)(kt & 1);
#pragma unroll
                for (int q = 0; q < 8; q++) {
                    uint32_t aB = HS(st) + (q >> 2) * 16384u + wm * 8192u
                                + (q & 3) * 512u + grp * 64u + tig * 16u;
                    uint32_t bB = HS(st) + 32768u + (q >> 2) * 1024u + (q & 3) * 256u
                                + (uint32_t)(wn * 8) * 2048u + grp * 32u + tig * 8u;
                    uint4 af[4]; uint2 bf[8];
#pragma unroll
                    for (int mi = 0; mi < 4; mi++) af[mi] = lds128u(aB + mi * 2048u);
#pragma unroll
                    for (int nj = 0; nj < 8; nj++) bf[nj] = lds64u(bB + nj * 2048u);
#pragma unroll
                    for (int mi = 0; mi < 4; mi++)
#pragma unroll
                        for (int nj = 0; nj < 8; nj++)
                            mma_f16(acc[mi][nj], af[mi], bf[nj]);
                }
            }

            // z(t) ready? add it
            BAR_SYNC(3, 256);
#pragma unroll
            for (int mi = 0; mi < 4; mi++)
#pragma unroll
                for (int njp = 0; njp < 4; njp++) {
                    uint4 zz = lds128u(zb + (mi * 4 + njp) * 16u);
                    float2 f0 = unph2(zz.x), f1 = unph2(zz.y);
                    float2 f2 = unph2(zz.z), f3 = unph2(zz.w);
                    acc[mi][2 * njp    ][0] += f0.x; acc[mi][2 * njp    ][1] += f0.y;
                    acc[mi][2 * njp    ][2] += f1.x; acc[mi][2 * njp    ][3] += f1.y;
                    acc[mi][2 * njp + 1][0] += f2.x; acc[mi][2 * njp + 1][1] += f2.y;
                    acc[mi][2 * njp + 1][2] += f3.x; acc[mi][2 * njp + 1][3] += f3.y;
                }

            // epilogue
            float hnv[2][8][2];
#pragma unroll
            for (int jhi = 0; jhi < 2; jhi++) {
                const int j = j0 + jhi * 8 + grp;
                const int kt_  = j >> 6;
                const int k16_ = (j >> 4) & 3;
                const int reg_ = (j >> 3) & 1;
                const int tig_ = (j >> 1) & 3;
                const int u_   = j & 1;
                const int jbase = (kt_ * 4 + k16_) * 32;
#pragma unroll
                for (int nj = 0; nj < 8; nj++) {
                    const int blk = by * 16 + wn * 8 + nj;
#pragma unroll
                    for (int e = 0; e < 2; e++) {
                        const int grp_b = tig * 2 + e;
                        float zi = acc[2 * jhi    ][nj][e]     + bia[jhi][0];
                        float zf = acc[2 * jhi    ][nj][2 + e] + bia[jhi][1];
                        float zg = acc[2 * jhi + 1][nj][e]     + bia[jhi][2];
                        float zo = acc[2 * jhi + 1][nj][2 + e] + bia[jhi][3];
                        float si = sigm_f(zi), sf = sigm_f(zf), so = sigm_f(zo);
                        float tg = tanh_f(zg);
                        float cn = sf * cr[jhi][nj][e] + si * tg;
                        float hn = so * tanh_f(cn);
                        cr[jhi][nj][e] = cn;
                        hnv[jhi][nj][e] = hn;
                        hw[(size_t)blk * 8192 + (jbase + grp_b * 4 + tig_) * 4
                           + reg_ * 2 + u_] = __float2half_rn(hn);
                    }
                }
            }

            BAR_SYNC(1, 128);
            if (tl == 0) {
                __threadfence();
                atomicAdd(&g_sync4[by], 1u);
            }
            BAR_ARRV(4, 256);   // z consumed; X may overwrite

            // out stores off the critical path
#pragma unroll
            for (int jhi = 0; jhi < 2; jhi++) {
                const int j = j0 + jhi * 8 + grp;
#pragma unroll
                for (int nj = 0; nj < 8; nj++) {
                    const int blk = by * 16 + wn * 8 + nj;
#pragma unroll
                    for (int e = 0; e < 2; e++) {
                        const int b = blk * 8 + tig * 2 + e;
                        out[(size_t)b * (TSTEPS * HIDDEN) + (size_t)t * 1024 + j]
                            = hnv[jhi][nj][e];
                    }
                }
            }
        }
        CP_WAIT0();
    }
}

// ------------------------------ launch ----------------------------------------
extern "C" void kernel_launch(void* const* d_in, const int* in_sizes, int n_in,
                              void* d_out, int out_size)
{
    const float* x    = (const float*)d_in[0];  // [512, 103, 1024]
    const float* W    = (const float*)d_in[1];  // [1024, 4096]
    const float* R    = (const float*)d_in[2];  // [1024, 4096]
    const float* bias = (const float*)d_in[3];  // [4096]
    float* out = (float*)d_out;                 // [512, 100, 1024]

    cudaFuncSetAttribute(lstm_persist, cudaFuncAttributeMaxDynamicSharedMemorySize, SMEM_SZ);

    const int total = N1 + N2 + N3 + 4;
    prep_all<<<(total + 255) / 256, 256>>>(W, R, x);

    dim3 grid(32, 4);   // 128 CTAs, 1/SM, co-resident
    lstm_persist<<<grid, 256, SMEM_SZ>>>(bias, out);
}

// round 15
// speedup vs baseline: 1.4889x; 1.2011x over previous
#include <cuda_runtime.h>
#include <cuda_fp16.h>
#include <cstdint>
#include <math.h>

#define HIDDEN   1024
#define BATCH    512
#define FEAT     1024
#define TSTEPS   100
#define TIME_TOT 103
#define FOURH    4096
#define MTOT     (TSTEPS * BATCH)   // 51200

// 2 stages x (A 32KB + B 16KB) = 96KB per CTA; 2 CTAs/SM = 192KB
#define STG_B    49152
#define SMEM_SZ  98304

// ------------------------------ scratch (device globals, no allocs) ----------
__device__ __align__(16) __half g_WRp[32 * 32 * 8192];         // [W;R] fp16 per-strip (16MB)
__device__ __align__(16) __half g_xp[(size_t)MTOT * 1024];     // permuted x fp16 (100MB)
__device__ __align__(16) __half g_hp[2][BATCH * HIDDEN];       // permuted h fp16 ping-pong
__device__ unsigned g_sync8[8];                                // per-by counters (8 groups)

// ------------------------------ asm helpers ----------------------------------
#define CP16(dst, src) \
    asm volatile("cp.async.cg.shared.global [%0], [%1], 16;" :: "r"(dst), "l"(src))
#define CP_COMMIT() asm volatile("cp.async.commit_group;" ::: "memory")
#define CP_WAIT1()  asm volatile("cp.async.wait_group 1;" ::: "memory")

__device__ __forceinline__ uint4 lds128u(uint32_t a) {
    uint4 v;
    asm volatile("ld.shared.v4.b32 {%0,%1,%2,%3}, [%4];"
                 : "=r"(v.x), "=r"(v.y), "=r"(v.z), "=r"(v.w) : "r"(a));
    return v;
}
__device__ __forceinline__ uint2 lds64u(uint32_t a) {
    uint2 v;
    asm volatile("ld.shared.v2.b32 {%0,%1}, [%2];" : "=r"(v.x), "=r"(v.y) : "r"(a));
    return v;
}
__device__ __forceinline__ void mma_f16(float c[4], uint4 a, uint2 b) {
    asm volatile(
        "mma.sync.aligned.m16n8k16.row.col.f32.f16.f16.f32 "
        "{%0,%1,%2,%3}, {%4,%5,%6,%7}, {%8,%9}, {%0,%1,%2,%3};"
        : "+f"(c[0]), "+f"(c[1]), "+f"(c[2]), "+f"(c[3])
        : "r"(a.x), "r"(a.y), "r"(a.z), "r"(a.w), "r"(b.x), "r"(b.y));
}

// fast transcendentals
__device__ __forceinline__ float sigm_f(float z) {
    return __fdividef(1.f, 1.f + __expf(-z));
}
__device__ __forceinline__ float tanh_f(float z) {
    return 1.f - __fdividef(2.f, __expf(2.f * z) + 1.f);
}

// ------------------------------ prep (single launch) --------------------------
#define N1 (32 * 32 * 4096)          // WRp half2 elems
#define N2 (MTOT * 1024 / 16)        // xp 16-float chunks
#define N3 (BATCH * HIDDEN / 2)      // hp[0] zero words

__global__ void prep_all(const float* __restrict__ W, const float* __restrict__ R,
                         const float* __restrict__ x)
{
    int idx = blockIdx.x * blockDim.x + threadIdx.x;
    if (idx < N1) {
        int v   = idx & 3;
        int tig = (idx >> 2) & 3;
        int grp = (idx >> 4) & 7;
        int k16 = (idx >> 7) & 3;
        int mi  = (idx >> 9) & 3;
        int wm  = (idx >> 11) & 1;
        int kt  = (idx >> 12) & 31;
        int cb  = idx >> 17;
        int r8  = v & 1;
        int khi = (v >> 1) * 8;
        int q   = mi * 2 + r8;
        int gate = q & 3;
        int jhi  = q >> 2;
        int j = cb * 32 + wm * 16 + jhi * 8 + grp;
        int kl = k16 * 16 + khi + 2 * tig;
        const float* src = (kt < 16) ? W : R;
        int k = (kt < 16 ? kt : kt - 16) * 64 + kl;
        int col = gate * 1024 + j;
        ((__half2*)g_WRp)[idx] = __floats2half2_rn(src[(size_t)k * FOURH + col],
                                                   src[(size_t)(k + 1) * FOURH + col]);
    } else if (idx < N1 + N2) {
        int id = idx - N1;
        int grp = id & 7;
        int k16 = (id >> 3) & 3;
        int kt  = (id >> 5) & 15;
        int blk = id >> 9;
        int m = blk * 8 + grp;
        int t = m >> 9, bb = m & 511;
        const float* s = x + ((size_t)bb * TIME_TOT + t) * FEAT + kt * 64 + k16 * 16;
        float f[16];
#pragma unroll
        for (int qd = 0; qd < 4; qd++) *(float4*)(f + qd * 4) = *(const float4*)(s + qd * 4);
        __half2 o[8];
#pragma unroll
        for (int tg = 0; tg < 4; tg++)
#pragma unroll
            for (int rg = 0; rg < 2; rg++)
                o[tg * 2 + rg] = __floats2half2_rn(f[rg * 8 + 2 * tg], f[rg * 8 + 2 * tg + 1]);
        __half2* d = (__half2*)g_xp + (size_t)blk * 4096 + kt * 256 + k16 * 64 + grp * 8;
        *(uint4*)d = *(uint4*)o;
        *(uint4*)(d + 4) = *(uint4*)(o + 4);
    } else if (idx < N1 + N2 + N3) {
        ((uint32_t*)g_hp)[idx - N1 - N2] = 0u;     // zero hp[0]
    } else if (idx < N1 + N2 + N3 + 8) {
        g_sync8[idx - N1 - N2 - N3] = 0u;
    }
}

// ------------------------------ pipeline pieces -------------------------------
// Stage: A (weights) 32KB @ +0, B (activations, 64 batch) 16KB @ +32768.
// ktile K covers k = K*128..K*128+127; K<8 = x-phase, K>=8 = h-phase.
// 128 threads issue; A: 16 chunks/thread, B: 8 chunks/thread.
#define ISSUE_STAGE(s, K, bxp, bhp) do {                                          \
    uint32_t _stA = sb + (uint32_t)(s) * STG_B;                                   \
    uint32_t _stB = _stA + 32768u;                                                \
    const char* _as = Abase + (size_t)(K) * 32768;                                \
    _Pragma("unroll")                                                             \
    for (int _r = 0; _r < 16; _r++) {                                             \
        int _id = tid + _r * 128;                                                 \
        CP16(_stA + _id * 16, _as + _id * 16);                                    \
    }                                                                             \
    const char* _bsrc = ((K) < 8) ? ((bxp) + (size_t)(K) * 2048)                  \
                                  : ((bhp) + (size_t)((K) - 8) * 2048);           \
    _Pragma("unroll")                                                             \
    for (int _r = 0; _r < 8; _r++) {                                              \
        int _c = tid + _r * 128;                                                  \
        CP16(_stB + _c * 16,                                                      \
             _bsrc + (size_t)(_c >> 7) * 16384 + (size_t)(_c & 127) * 16);        \
    }                                                                             \
} while (0)

// A: [sub(2):16384][wm:8192][mi:2048][k16:512][grp:64][tig:16]
// B: [blk(8):2048][sub(2):1024][k16:256][grp:32][tig:8]; warp covers wn*4+nj blks
#define COMPUTE_STAGE(s) do {                                                     \
    uint32_t _aB = sb + (uint32_t)(s) * STG_B + wm * 8192u + grp * 64u + tig * 16u; \
    uint32_t _bB = sb + (uint32_t)(s) * STG_B + 32768u + wn * 8192u + grp * 32u + tig * 8u; \
    uint4 _af[2][4]; uint2 _bf[2][4];                                             \
    _Pragma("unroll")                                                             \
    for (int _mi = 0; _mi < 4; _mi++) _af[0][_mi] = lds128u(_aB + _mi * 2048);    \
    _Pragma("unroll")                                                             \
    for (int _nj = 0; _nj < 4; _nj++) _bf[0][_nj] = lds64u(_bB + _nj * 2048);     \
    _Pragma("unroll")                                                             \
    for (int _k = 0; _k < 8; _k++) {                                              \
        const int _cur = _k & 1, _nxt = _cur ^ 1;                                 \
        if (_k < 7) {                                                             \
            const uint32_t _ao = ((_k + 1) >> 2) * 16384u + ((_k + 1) & 3) * 512u; \
            const uint32_t _bo = ((_k + 1) >> 2) * 1024u  + ((_k + 1) & 3) * 256u; \
            _Pragma("unroll")                                                     \
            for (int _mi = 0; _mi < 4; _mi++)                                     \
                _af[_nxt][_mi] = lds128u(_aB + _ao + _mi * 2048);                 \
            _Pragma("unroll")                                                     \
            for (int _nj = 0; _nj < 4; _nj++)                                     \
                _bf[_nxt][_nj] = lds64u(_bB + _bo + _nj * 2048);                  \
        }                                                                         \
        _Pragma("unroll")                                                         \
        for (int _mi = 0; _mi < 4; _mi++)                                         \
            _Pragma("unroll")                                                     \
            for (int _nj = 0; _nj < 4; _nj++)                                     \
                mma_f16(acc[_mi][_nj], _af[_cur][_mi], _bf[_cur][_nj]);           \
    }                                                                             \
} while (0)

// ------------------------------ persistent fused LSTM -------------------------
// grid (32,8), 128 thr/CTA, 2 CTAs/SM. cb = 32-hidden strip, by = 64-batch block.
// Two independent CTAs per SM interleave: one's barriers/epilogue/spin hide
// behind the other's MMAs. Tile 128(gates)x64(batch), warp tile 64x32.
__global__ void __launch_bounds__(128, 2)
lstm_persist(const float* __restrict__ bias, float* __restrict__ out)
{
    extern __shared__ char smem[];
    const uint32_t sb = (uint32_t)__cvta_generic_to_shared(smem);
    const int tid = threadIdx.x, lane = tid & 31, wid = tid >> 5;
    const int wm = wid >> 1, wn = wid & 1;
    const int grp = lane >> 2, tig = lane & 3;
    const int cb = blockIdx.x, by = blockIdx.y;

    const char* Abase = (const char*)g_WRp + (size_t)cb * 524288;
    const size_t bblk0 = (size_t)(by * 8) * 16384;

    const int j0 = cb * 32 + wm * 16;
    float bia[2][4];
#pragma unroll
    for (int jhi = 0; jhi < 2; jhi++) {
        const int j = j0 + jhi * 8 + grp;
        bia[jhi][0] = __ldg(bias + j);
        bia[jhi][1] = __ldg(bias + 1024 + j);
        bia[jhi][2] = __ldg(bias + 2048 + j);
        bia[jhi][3] = __ldg(bias + 3072 + j);
    }
    float cr[2][4][2];
#pragma unroll
    for (int a = 0; a < 2; a++)
#pragma unroll
        for (int b = 0; b < 4; b++) { cr[a][b][0] = 0.f; cr[a][b][1] = 0.f; }

    // prologue: K=0 of t=0 -> stage 0
    {
        const char* Bx = (const char*)g_xp + bblk0;
        const char* Bh = (const char*)g_hp[0] + bblk0;
        ISSUE_STAGE(0, 0, Bx, Bh); CP_COMMIT();
    }

    for (int t = 0; t < TSTEPS; t++) {
        const char* Bx  = (const char*)g_xp + (size_t)t * 64 * 16384 + bblk0;
        const char* Bh  = (const char*)g_hp[t & 1] + bblk0;
        const char* BxN = Bx + (size_t)64 * 16384;
        __half* hw = g_hp[(t & 1) ^ 1];

        float acc[4][4][4];
#pragma unroll
        for (int a = 0; a < 4; a++)
#pragma unroll
            for (int b = 0; b < 4; b++)
#pragma unroll
                for (int c = 0; c < 4; c++) acc[a][b][c] = 0.f;

        for (int kt = 0; kt < 16; kt++) {
            __syncthreads();               // all warps done computing kt-1
            if (kt == 7 && t > 0) {
                // h needed from K=8 on; every thread spins
                const unsigned tgt = (unsigned)t * 32u;
                while (*(volatile unsigned*)&g_sync8[by] < tgt) { }
                __threadfence();
            }
            const int la = kt + 1;
            if (la < 16) {
                ISSUE_STAGE(la & 1, la, Bx, Bh);
            } else if (t + 1 < TSTEPS) {
                ISSUE_STAGE(0, 0, BxN, Bh);   // next step's K=0 (x-phase)
            }
            CP_COMMIT();
            CP_WAIT1();                    // own copies of K=kt landed
            __syncthreads();               // everyone's copies landed
            COMPUTE_STAGE(kt & 1);
        }

        // ---- fused LSTM epilogue (c in registers) ----
        float hnv[2][4][2];
#pragma unroll
        for (int jhi = 0; jhi < 2; jhi++) {
            const int j = j0 + jhi * 8 + grp;
            const int kt_  = j >> 6;
            const int k16_ = (j >> 4) & 3;
            const int reg_ = (j >> 3) & 1;
            const int tig_ = (j >> 1) & 3;
            const int u_   = j & 1;
            const int jbase = (kt_ * 4 + k16_) * 32;
#pragma unroll
            for (int nj = 0; nj < 4; nj++) {
                const int blk = by * 8 + wn * 4 + nj;
#pragma unroll
                for (int e = 0; e < 2; e++) {
                    const int grp_b = tig * 2 + e;
                    float zi = acc[2 * jhi    ][nj][e]     + bia[jhi][0];
                    float zf = acc[2 * jhi    ][nj][2 + e] + bia[jhi][1];
                    float zg = acc[2 * jhi + 1][nj][e]     + bia[jhi][2];
                    float zo = acc[2 * jhi + 1][nj][2 + e] + bia[jhi][3];

                    float si = sigm_f(zi);
                    float sf = sigm_f(zf);
                    float so = sigm_f(zo);
                    float tg = tanh_f(zg);

                    float cn = sf * cr[jhi][nj][e] + si * tg;
                    float hn = so * tanh_f(cn);
                    cr[jhi][nj][e] = cn;
                    hnv[jhi][nj][e] = hn;
                    hw[(size_t)blk * 8192 + (jbase + grp_b * 4 + tig_) * 4 + reg_ * 2 + u_] =
                        __float2half_rn(hn);
                }
            }
        }

        // publish h, arrive on group counter, then out stores (off critical path)
        __syncthreads();
        if (tid == 0) {
            __threadfence();
            atomicAdd(&g_sync8[by], 1u);
        }

#pragma unroll
        for (int jhi = 0; jhi < 2; jhi++) {
            const int j = j0 + jhi * 8 + grp;
#pragma unroll
            for (int nj = 0; nj < 4; nj++) {
                const int blk = by * 8 + wn * 4 + nj;
#pragma unroll
                for (int e = 0; e < 2; e++) {
                    const int b = blk * 8 + tig * 2 + e;
                    out[(size_t)b * (TSTEPS * HIDDEN) + (size_t)t * 1024 + j] = hnv[jhi][nj][e];
                }
            }
        }
    }
}

// ------------------------------ launch ----------------------------------------
extern "C" void kernel_launch(void* const* d_in, const int* in_sizes, int n_in,
                              void* d_out, int out_size)
{
    const float* x    = (const float*)d_in[0];  // [512, 103, 1024]
    const float* W    = (const float*)d_in[1];  // [1024, 4096]
    const float* R    = (const float*)d_in[2];  // [1024, 4096]
    const float* bias = (const float*)d_in[3];  // [4096]
    float* out = (float*)d_out;                 // [512, 100, 1024]

    cudaFuncSetAttribute(lstm_persist, cudaFuncAttributeMaxDynamicSharedMemorySize, SMEM_SZ);

    const int total = N1 + N2 + N3 + 8;
    prep_all<<<(total + 255) / 256, 256>>>(W, R, x);

    dim3 grid(32, 8);   // 256 CTAs, 2/SM target, all co-resident (<= 296)
    lstm_persist<<<grid, 128, SMEM_SZ>>>(bias, out);
}